// round 6
// baseline (speedup 1.0000x reference)
#include <cuda_runtime.h>
#include <cstdint>

typedef unsigned long long ull;

// ---- packed f32x2 helpers (sm_103a) ----
__device__ __forceinline__ ull ffma2(ull a, ull b, ull c) {
    ull d;
    asm("fma.rn.f32x2 %0, %1, %2, %3;" : "=l"(d) : "l"(a), "l"(b), "l"(c));
    return d;
}
__device__ __forceinline__ ull fmul2(ull a, ull b) {
    ull d;
    asm("mul.rn.f32x2 %0, %1, %2;" : "=l"(d) : "l"(a), "l"(b));
    return d;
}
__device__ __forceinline__ ull fadd2(ull a, ull b) {
    ull d;
    asm("add.rn.f32x2 %0, %1, %2;" : "=l"(d) : "l"(a), "l"(b));
    return d;
}
__device__ __forceinline__ ull pack2(float lo, float hi) {
    ull d;
    asm("mov.b64 %0, {%1, %2};" : "=l"(d) : "f"(lo), "f"(hi));
    return d;
}
__device__ __forceinline__ ull dup2(float v) { return pack2(v, v); }
__device__ __forceinline__ float2 unpack2(ull v) {
    float lo, hi;
    asm("mov.b64 {%0, %1}, %2;" : "=f"(lo), "=f"(hi) : "l"(v));
    return make_float2(lo, hi);
}
__device__ __forceinline__ ull shflx(ull v, int m) {
    return __shfl_xor_sync(0xffffffffu, v, m);
}

constexpr int D_DIM        = 1024;
constexpr int THREADS      = 256;
constexpr int ROWS_PER_BLK = 64;
constexpr int BATCH        = 16;                 // rows per barrier batch
constexpr int NBATCH       = ROWS_PER_BLK / BATCH;
constexpr int NGRP         = 16;                 // 16-lane groups over 256 threads
constexpr int SLOTS        = BATCH * 3;          // 48 (row, f32x2-pair)
constexpr int GSTRIDE      = NGRP + 1;           // 17, pad vs bank conflicts

// compute 4 rows from xv[0..3], 4-round butterfly, STS group sums (slot-major)
__device__ __forceinline__ void compute4(const float4* xv, const ull wp[4][3],
                                         ull* pbase, int row0,
                                         int lane, int warp) {
    #pragma unroll
    for (int u = 0; u < 4; ++u) {
        ull xx = dup2(xv[u].x);
        ull a0 = fmul2(xx, wp[0][0]);
        ull a1 = fmul2(xx, wp[0][1]);
        ull a2 = fmul2(xx, wp[0][2]);
        xx = dup2(xv[u].y);
        a0 = ffma2(xx, wp[1][0], a0);
        a1 = ffma2(xx, wp[1][1], a1);
        a2 = ffma2(xx, wp[1][2], a2);
        xx = dup2(xv[u].z);
        a0 = ffma2(xx, wp[2][0], a0);
        a1 = ffma2(xx, wp[2][1], a1);
        a2 = ffma2(xx, wp[2][2], a2);
        xx = dup2(xv[u].w);
        a0 = ffma2(xx, wp[3][0], a0);
        a1 = ffma2(xx, wp[3][1], a1);
        a2 = ffma2(xx, wp[3][2], a2);

        // 4-round butterfly: lane%16==0 holds 16-lane group sum
        a0 = fadd2(a0, shflx(a0, 1));
        a1 = fadd2(a1, shflx(a1, 1));
        a2 = fadd2(a2, shflx(a2, 1));
        a0 = fadd2(a0, shflx(a0, 2));
        a1 = fadd2(a1, shflx(a1, 2));
        a2 = fadd2(a2, shflx(a2, 2));
        a0 = fadd2(a0, shflx(a0, 4));
        a1 = fadd2(a1, shflx(a1, 4));
        a2 = fadd2(a2, shflx(a2, 4));
        a0 = fadd2(a0, shflx(a0, 8));
        a1 = fadd2(a1, shflx(a1, 8));
        a2 = fadd2(a2, shflx(a2, 8));

        if ((lane & 15) == 0) {
            const int g = (warp << 1) | (lane >> 4);     // 0..15
            const int s = (row0 + u) * 3;                // slot base
            pbase[(s + 0) * GSTRIDE + g] = a0;
            pbase[(s + 1) * GSTRIDE + g] = a1;
            pbase[(s + 2) * GSTRIDE + g] = a2;
        }
    }
}

__global__ void __launch_bounds__(THREADS)
q6_kernel(const float* __restrict__ x,
          const float* __restrict__ W,
          const float* __restrict__ proto,
          const float* __restrict__ hs,
          float* __restrict__ out)
{
    __shared__ ull   part[2][SLOTS * GSTRIDE];   // 2 x 6.4KB
    __shared__ float pn[8][6];
    __shared__ float s3_sh;

    const int tid  = threadIdx.x;
    const int lane = tid & 31;
    const int warp = tid >> 5;
    const int col  = tid * 4;          // this thread owns columns [col, col+4)

    // ---- one-time block init (ordered by first batch's __syncthreads) ----
    if (tid < 8) {
        float v[6]; float ss = 0.f;
        #pragma unroll
        for (int k = 0; k < 6; ++k) { v[k] = proto[tid * 6 + k]; ss += v[k] * v[k]; }
        float n = fmaxf(sqrtf(ss), 1e-12f);
        #pragma unroll
        for (int k = 0; k < 6; ++k) pn[tid][k] = v[k] / n;
    }
    if (tid == 8) s3_sh = 3.0f * hs[0];   // softmax(-hs*(6-6d)/2) == softmax(3*hs*d)

    // ---- W slice: 4 columns, packed (k0,k1),(k2,k3),(k4,k5) ----
    ull wp[4][3];
    {
        float4 w4[6];
        #pragma unroll
        for (int k = 0; k < 6; ++k)
            w4[k] = *reinterpret_cast<const float4*>(W + k * D_DIM + col);
        #pragma unroll
        for (int p = 0; p < 3; ++p) {
            wp[0][p] = pack2(w4[2*p].x, w4[2*p+1].x);
            wp[1][p] = pack2(w4[2*p].y, w4[2*p+1].y);
            wp[2][p] = pack2(w4[2*p].z, w4[2*p+1].z);
            wp[3][p] = pack2(w4[2*p].w, w4[2*p+1].w);
        }
    }

    const int    rowbase = blockIdx.x * ROWS_PER_BLK;
    const float* xp      = x + (size_t)rowbase * D_DIM + col;

    // prime: batch 0 rows 0..3
    float4 xa[4], xb[4];
    #pragma unroll
    for (int u = 0; u < 4; ++u)
        xa[u] = __ldcs(reinterpret_cast<const float4*>(xp + (size_t)u * D_DIM));

    #pragma unroll 1
    for (int b = 0; b < NBATCH; ++b) {
        ull* pbase = part[b & 1];
        const float* xrow = xp + (size_t)(b * BATCH) * D_DIM;

        // rolling prefetch: always 4 LDG.128 in flight during each compute4
        #pragma unroll
        for (int u = 0; u < 4; ++u)
            xb[u] = __ldcs(reinterpret_cast<const float4*>(xrow + (size_t)(4 + u) * D_DIM));
        compute4(xa, wp, pbase, 0, lane, warp);

        #pragma unroll
        for (int u = 0; u < 4; ++u)
            xa[u] = __ldcs(reinterpret_cast<const float4*>(xrow + (size_t)(8 + u) * D_DIM));
        compute4(xb, wp, pbase, 4, lane, warp);

        #pragma unroll
        for (int u = 0; u < 4; ++u)
            xb[u] = __ldcs(reinterpret_cast<const float4*>(xrow + (size_t)(12 + u) * D_DIM));
        compute4(xa, wp, pbase, 8, lane, warp);

        if (b + 1 < NBATCH) {   // next batch rows 0..3 — stay in flight across barrier
            #pragma unroll
            for (int u = 0; u < 4; ++u)
                xa[u] = __ldcs(reinterpret_cast<const float4*>(xrow + (size_t)(16 + u) * D_DIM));
        }
        compute4(xb, wp, pbase, 12, lane, warp);

        __syncthreads();   // all partials of batch b visible; also gates reuse of
                           // part[b&1] against batch b-2's reduce reads (program order)

        // ---- distributed reduce: warp w owns rows 2w, 2w+1 (slots 6w..6w+5) ----
        ull zs[6];
        {
            const int sbase = warp * 6;
            #pragma unroll
            for (int j = 0; j < 6; ++j) {
                ull v = (lane < NGRP) ? pbase[(sbase + j) * GSTRIDE + lane] : 0ull;
                v = fadd2(v, shflx(v, 8));
                v = fadd2(v, shflx(v, 4));
                v = fadd2(v, shflx(v, 2));
                v = fadd2(v, shflx(v, 1));
                zs[j] = v;     // all lanes hold slot sum
            }
        }

        // ---- epilogue: lanes 0,1 handle rows 2w, 2w+1 ----
        if (lane < 2) {
            float z[6];
            #pragma unroll
            for (int p = 0; p < 3; ++p) {
                float2 v = unpack2(zs[lane * 3 + p]);
                z[2*p] = v.x; z[2*p + 1] = v.y;
            }
            float ss = 0.f;
            #pragma unroll
            for (int k = 0; k < 6; ++k) {
                float e2 = __expf(2.0f * z[k]);           // tanh = 1 - 2/(e^2x+1)
                z[k] = 1.0f - __fdividef(2.0f, e2 + 1.0f);
                ss += z[k] * z[k];
            }
            const float sc = __fdividef(s3_sh, fmaxf(sqrtf(ss), 1e-6f));

            float e[8]; float esum = 0.f;
            #pragma unroll
            for (int p = 0; p < 8; ++p) {
                float d = 0.f;
                #pragma unroll
                for (int k = 0; k < 6; ++k) d += z[k] * pn[p][k];
                e[p] = __expf(sc * d);
                esum += e[p];
            }
            const float rs  = __fdividef(1.0f, esum);
            const int   row = rowbase + b * BATCH + warp * 2 + lane;
            float4* op = reinterpret_cast<float4*>(out + (size_t)row * 8);
            op[0] = make_float4(e[0]*rs, e[1]*rs, e[2]*rs, e[3]*rs);
            op[1] = make_float4(e[4]*rs, e[5]*rs, e[6]*rs, e[7]*rs);
        }
    }
}

extern "C" void kernel_launch(void* const* d_in, const int* in_sizes, int n_in,
                              void* d_out, int out_size) {
    const float* x     = (const float*)d_in[0];
    const float* W     = (const float*)d_in[1];
    const float* proto = (const float*)d_in[2];
    const float* hs    = (const float*)d_in[3];
    float* out = (float*)d_out;

    const int n_rows = in_sizes[0] / D_DIM;      // 32768
    const int grid   = n_rows / ROWS_PER_BLK;    // 512
    q6_kernel<<<grid, THREADS>>>(x, W, proto, hs, out);
}

// round 7
// speedup vs baseline: 1.5445x; 1.5445x over previous
#include <cuda_runtime.h>
#include <cstdint>

typedef unsigned long long ull;

// ---- packed f32x2 helpers (sm_103a) ----
__device__ __forceinline__ ull ffma2(ull a, ull b, ull c) {
    ull d;
    asm("fma.rn.f32x2 %0, %1, %2, %3;" : "=l"(d) : "l"(a), "l"(b), "l"(c));
    return d;
}
__device__ __forceinline__ ull fmul2(ull a, ull b) {
    ull d;
    asm("mul.rn.f32x2 %0, %1, %2;" : "=l"(d) : "l"(a), "l"(b));
    return d;
}
__device__ __forceinline__ ull fadd2(ull a, ull b) {
    ull d;
    asm("add.rn.f32x2 %0, %1, %2;" : "=l"(d) : "l"(a), "l"(b));
    return d;
}
__device__ __forceinline__ ull pack2(float lo, float hi) {
    ull d;
    asm("mov.b64 %0, {%1, %2};" : "=l"(d) : "f"(lo), "f"(hi));
    return d;
}
__device__ __forceinline__ ull dup2(float v) { return pack2(v, v); }
__device__ __forceinline__ float2 unpack2(ull v) {
    float lo, hi;
    asm("mov.b64 {%0, %1}, %2;" : "=f"(lo), "=f"(hi) : "l"(v));
    return make_float2(lo, hi);
}
__device__ __forceinline__ ull shflx(ull v, int m) {
    return __shfl_xor_sync(0xffffffffu, v, m);
}

constexpr int D_DIM        = 1024;
constexpr int THREADS      = 256;
constexpr int ROWS_PER_BLK = 64;
constexpr int BATCH        = 16;                 // rows per barrier batch
constexpr int NBATCH       = ROWS_PER_BLK / BATCH;
constexpr int NGRP         = 32;                 // 8-lane groups over 256 threads
constexpr int SLOTS        = BATCH * 3;          // 48 (row, f32x2-pair)
constexpr int PSTRIDE      = SLOTS + 1;          // 49, odd stride vs bank conflicts

// compute 2 rows from xv[0..1]; 3-round butterfly; STS group sums
__device__ __forceinline__ void compute2(const float4* xv, const ull wp[4][3],
                                         ull* pbase, int row0,
                                         int lane, int warp) {
    #pragma unroll
    for (int u = 0; u < 2; ++u) {
        ull xx = dup2(xv[u].x);
        ull a0 = fmul2(xx, wp[0][0]);
        ull a1 = fmul2(xx, wp[0][1]);
        ull a2 = fmul2(xx, wp[0][2]);
        xx = dup2(xv[u].y);
        a0 = ffma2(xx, wp[1][0], a0);
        a1 = ffma2(xx, wp[1][1], a1);
        a2 = ffma2(xx, wp[1][2], a2);
        xx = dup2(xv[u].z);
        a0 = ffma2(xx, wp[2][0], a0);
        a1 = ffma2(xx, wp[2][1], a1);
        a2 = ffma2(xx, wp[2][2], a2);
        xx = dup2(xv[u].w);
        a0 = ffma2(xx, wp[3][0], a0);
        a1 = ffma2(xx, wp[3][1], a1);
        a2 = ffma2(xx, wp[3][2], a2);

        // 3-round butterfly: lane%8==0 holds 8-lane (32-column) group sum
        a0 = fadd2(a0, shflx(a0, 1));
        a1 = fadd2(a1, shflx(a1, 1));
        a2 = fadd2(a2, shflx(a2, 1));
        a0 = fadd2(a0, shflx(a0, 2));
        a1 = fadd2(a1, shflx(a1, 2));
        a2 = fadd2(a2, shflx(a2, 2));
        a0 = fadd2(a0, shflx(a0, 4));
        a1 = fadd2(a1, shflx(a1, 4));
        a2 = fadd2(a2, shflx(a2, 4));

        if ((lane & 7) == 0) {
            const int g = warp * 4 + (lane >> 3);    // 0..31
            ull* dst = pbase + g * PSTRIDE + (row0 + u) * 3;
            dst[0] = a0; dst[1] = a1; dst[2] = a2;
        }
    }
}

__global__ void __launch_bounds__(THREADS)
q6_kernel(const float* __restrict__ x,
          const float* __restrict__ W,
          const float* __restrict__ proto,
          const float* __restrict__ hs,
          float* __restrict__ out)
{
    __shared__ ull   part[NGRP * PSTRIDE];   // 12.25 KB
    __shared__ ull   zz[BATCH * 3];
    __shared__ float pn[8][6];
    __shared__ float s3_sh;

    const int tid  = threadIdx.x;
    const int lane = tid & 31;
    const int warp = tid >> 5;
    const int col  = tid * 4;          // this thread owns columns [col, col+4)

    // ---- one-time block init (visible after first batch's barrier) ----
    if (tid < 8) {
        float v[6]; float ss = 0.f;
        #pragma unroll
        for (int k = 0; k < 6; ++k) { v[k] = proto[tid * 6 + k]; ss += v[k] * v[k]; }
        float n = fmaxf(sqrtf(ss), 1e-12f);
        #pragma unroll
        for (int k = 0; k < 6; ++k) pn[tid][k] = v[k] / n;
    }
    if (tid == 8) s3_sh = 3.0f * hs[0];   // softmax(-hs*(6-6d)/2) == softmax(3*hs*d)

    // ---- W slice: 4 columns, packed (k0,k1),(k2,k3),(k4,k5) ----
    ull wp[4][3];
    {
        float4 w4[6];
        #pragma unroll
        for (int k = 0; k < 6; ++k)
            w4[k] = *reinterpret_cast<const float4*>(W + k * D_DIM + col);
        #pragma unroll
        for (int p = 0; p < 3; ++p) {
            wp[0][p] = pack2(w4[2*p].x, w4[2*p+1].x);
            wp[1][p] = pack2(w4[2*p].y, w4[2*p+1].y);
            wp[2][p] = pack2(w4[2*p].z, w4[2*p+1].z);
            wp[3][p] = pack2(w4[2*p].w, w4[2*p+1].w);
        }
    }

    const int    rowbase = blockIdx.x * ROWS_PER_BLK;
    const float* xp      = x + (size_t)rowbase * D_DIM + col;

    // prime: rows 0,1
    float4 xa[2], xb[2];
    xa[0] = __ldcs(reinterpret_cast<const float4*>(xp));
    xa[1] = __ldcs(reinterpret_cast<const float4*>(xp + D_DIM));

    #pragma unroll 1
    for (int b = 0; b < NBATCH; ++b) {
        const float* xrow = xp + (size_t)(b * BATCH) * D_DIM;

        // 8 pairs; alternate xa/xb so 2 LDG.128 are ALWAYS in flight
        #pragma unroll
        for (int p = 0; p < 8; p += 2) {
            // load pair p+1 into xb, compute pair p from xa
            xb[0] = __ldcs(reinterpret_cast<const float4*>(xrow + (size_t)(2*p + 2) * D_DIM));
            xb[1] = __ldcs(reinterpret_cast<const float4*>(xrow + (size_t)(2*p + 3) * D_DIM));
            compute2(xa, wp, part, 2*p, lane, warp);

            // load pair p+2 into xa (crosses into next batch at p==6), compute pair p+1
            if (p < 6 || b + 1 < NBATCH) {
                xa[0] = __ldcs(reinterpret_cast<const float4*>(xrow + (size_t)(2*p + 4) * D_DIM));
                xa[1] = __ldcs(reinterpret_cast<const float4*>(xrow + (size_t)(2*p + 5) * D_DIM));
            }
            compute2(xb, wp, part, 2*p + 2, lane, warp);
        }

        __syncthreads();   // all partials of batch b visible

        // ---- phase 2: 48 threads sum 32 group partials per (row, pair) ----
        if (tid < SLOTS) {
            ull s0 = 0ull, s1 = 0ull, s2 = 0ull, s3v = 0ull;
            #pragma unroll
            for (int g = 0; g < NGRP; g += 4) {
                s0  = fadd2(s0,  part[(g + 0) * PSTRIDE + tid]);
                s1  = fadd2(s1,  part[(g + 1) * PSTRIDE + tid]);
                s2  = fadd2(s2,  part[(g + 2) * PSTRIDE + tid]);
                s3v = fadd2(s3v, part[(g + 3) * PSTRIDE + tid]);
            }
            zz[tid] = fadd2(fadd2(s0, s1), fadd2(s2, s3v));
        }
        __syncthreads();   // zz visible; also gates part reuse by next batch

        // ---- phase 3: one thread per row (overlaps next batch's streaming) ----
        if (tid < BATCH) {
            float z[6];
            #pragma unroll
            for (int p = 0; p < 3; ++p) {
                float2 v = unpack2(zz[tid * 3 + p]);
                z[2*p] = v.x; z[2*p + 1] = v.y;
            }
            float ss = 0.f;
            #pragma unroll
            for (int k = 0; k < 6; ++k) {
                float e2 = __expf(2.0f * z[k]);           // tanh = 1 - 2/(e^2x+1)
                z[k] = 1.0f - __fdividef(2.0f, e2 + 1.0f);
                ss += z[k] * z[k];
            }
            const float sc = __fdividef(s3_sh, fmaxf(sqrtf(ss), 1e-6f));

            float e[8]; float esum = 0.f;
            #pragma unroll
            for (int p = 0; p < 8; ++p) {
                float d = 0.f;
                #pragma unroll
                for (int k = 0; k < 6; ++k) d += z[k] * pn[p][k];
                e[p] = __expf(sc * d);
                esum += e[p];
            }
            const float rs  = __fdividef(1.0f, esum);
            const int   row = rowbase + b * BATCH + tid;
            float4* op = reinterpret_cast<float4*>(out + (size_t)row * 8);
            op[0] = make_float4(e[0]*rs, e[1]*rs, e[2]*rs, e[3]*rs);
            op[1] = make_float4(e[4]*rs, e[5]*rs, e[6]*rs, e[7]*rs);
        }
    }
}

extern "C" void kernel_launch(void* const* d_in, const int* in_sizes, int n_in,
                              void* d_out, int out_size) {
    const float* x     = (const float*)d_in[0];
    const float* W     = (const float*)d_in[1];
    const float* proto = (const float*)d_in[2];
    const float* hs    = (const float*)d_in[3];
    float* out = (float*)d_out;

    const int n_rows = in_sizes[0] / D_DIM;      // 32768
    const int grid   = n_rows / ROWS_PER_BLK;    // 512
    q6_kernel<<<grid, THREADS>>>(x, W, proto, hs, out);
}